// round 14
// baseline (speedup 1.0000x reference)
#include <cuda_runtime.h>
#include <cuda_fp16.h>
#include <cstdint>

// ExpertScatter: out[b, Ind[b,h,k], :] += Y[b,h,k,:] @ W[h]
// R14: R13 platform + Y pre-converted to fp16 in prologue -> A staging is
//      pure cp.async (instruction-count cut). fp16 mma, TM=128/TN=128,
//      256 thr, 2 CTAs/SM, red.v2 epilogue.

#define BB 8
#define HH 16
#define KDIM 1024
#define DD 128
#define NN 1024
#define TT 4096

#define TM 128
#define TN 128
#define NCHUNK 8
#define THREADS 256

#define AS_BYTES (TM * DD * 2)                 // 32768
#define BS_BYTES (DD * TN * 2)                 // 32768
#define SMEM_BYTES (AS_BYTES + 2 * BS_BYTES)   // 98304 (2 CTAs = 192KB)

__device__ __align__(16) __half g_Wh[HH * DD * NN];          // 4 MB
__device__ __align__(16) __half g_Yh[BB * HH * KDIM * DD];   // 33.5 MB

__device__ __forceinline__ uint32_t pack_h2(float a, float b) {
    __half2 h = __floats2half2_rn(a, b);
    return *(uint32_t*)&h;
}

// fused prologue: [0,512) convert W ; [512, 4608) convert Y ; rest zero out
#define WCONV_BLOCKS 512
#define YCONV_BLOCKS 4096
__global__ void prologue_kernel(const float* __restrict__ W, __half* __restrict__ Wh,
                                const float* __restrict__ Y, __half* __restrict__ Yh,
                                float4* __restrict__ out, int nzero4) {
    const int bx = blockIdx.x;
    if (bx < WCONV_BLOCKS) {
        const int i = bx * 512 + threadIdx.x;            // 262144 uint4
        const float4 v0 = ((const float4*)W)[2 * i];
        const float4 v1 = ((const float4*)W)[2 * i + 1];
        uint4 w = { pack_h2(v0.x, v0.y), pack_h2(v0.z, v0.w),
                    pack_h2(v1.x, v1.y), pack_h2(v1.z, v1.w) };
        ((uint4*)Wh)[i] = w;
    } else if (bx < WCONV_BLOCKS + YCONV_BLOCKS) {
        const int i = (bx - WCONV_BLOCKS) * 512 + threadIdx.x;   // 2097152 uint4
        const float4 v0 = ((const float4*)Y)[2 * i];
        const float4 v1 = ((const float4*)Y)[2 * i + 1];
        uint4 w = { pack_h2(v0.x, v0.y), pack_h2(v0.z, v0.w),
                    pack_h2(v1.x, v1.y), pack_h2(v1.z, v1.w) };
        ((uint4*)Yh)[i] = w;
    } else {
        const int j = (bx - WCONV_BLOCKS - YCONV_BLOCKS) * 512 + threadIdx.x;
        if (j < nzero4) out[j] = make_float4(0.f, 0.f, 0.f, 0.f);
    }
}

__device__ __forceinline__ uint32_t smem_u32(const void* p) {
    uint32_t a;
    asm("{ .reg .u64 t; cvta.to.shared.u64 t, %1; cvt.u32.u64 %0, t; }" : "=r"(a) : "l"(p));
    return a;
}
__device__ __forceinline__ void cp16(uint32_t dst, const void* src) {
    asm volatile("cp.async.cg.shared.global [%0], [%1], 16;" :: "r"(dst), "l"(src));
}
#define CP_COMMIT() asm volatile("cp.async.commit_group;" ::: "memory")
#define CP_WAIT0()  asm volatile("cp.async.wait_group 0;" ::: "memory")

__device__ __forceinline__ void ldsm_x4(uint32_t* r, uint32_t addr) {
    asm volatile("ldmatrix.sync.aligned.m8n8.x4.shared.b16 {%0,%1,%2,%3}, [%4];"
                 : "=r"(r[0]), "=r"(r[1]), "=r"(r[2]), "=r"(r[3]) : "r"(addr));
}
__device__ __forceinline__ void ldsm_x4_t(uint32_t* r, uint32_t addr) {
    asm volatile("ldmatrix.sync.aligned.m8n8.x4.trans.shared.b16 {%0,%1,%2,%3}, [%4];"
                 : "=r"(r[0]), "=r"(r[1]), "=r"(r[2]), "=r"(r[3]) : "r"(addr));
}
__device__ __forceinline__ void mma_f16(float* c, const uint32_t* a, const uint32_t* b) {
    asm volatile(
        "mma.sync.aligned.m16n8k16.row.col.f32.f16.f16.f32 "
        "{%0,%1,%2,%3}, {%4,%5,%6,%7}, {%8,%9}, {%0,%1,%2,%3};"
        : "+f"(c[0]), "+f"(c[1]), "+f"(c[2]), "+f"(c[3])
        : "r"(a[0]), "r"(a[1]), "r"(a[2]), "r"(a[3]), "r"(b[0]), "r"(b[1]));
}
__device__ __forceinline__ void red_v2(float* p, float x, float y) {
    asm volatile("red.global.add.v2.f32 [%0], {%1, %2};"
                 :: "l"(p), "f"(x), "f"(y) : "memory");
}

__global__ void __launch_bounds__(THREADS, 2)
expert_scatter_f16(const int* __restrict__ Ind,
                   float*     __restrict__ out) {
    const int b  = blockIdx.z;
    const int h  = blockIdx.y;
    const int k0 = blockIdx.x * TM;

    extern __shared__ char sm[];
    const uint32_t As_a = smem_u32(sm);
    const uint32_t Bs_a[2] = { As_a + AS_BYTES, As_a + AS_BYTES + BS_BYTES };
    __shared__ int sInd[TM];

    const int tid  = threadIdx.x;
    const int warp = tid >> 5;
    const int lane = tid & 31;
    const int g    = lane >> 2;
    const int tig  = lane & 3;
    const int wm   = warp >> 2;   // 0..1 : 64-row band
    const int wn   = warp & 3;    // 0..3 : 32-col band

    const __half* Wsrc = g_Wh + (size_t)h * DD * NN;
    const __half* Ysrc = g_Yh + ((size_t)(b * HH + h) * KDIM + k0) * DD;

    // ---- Prologue staging: B chunk 0 + A tile, all cp.async, one group ----
    #pragma unroll
    for (int i = 0; i < 8; i++) {
        const int flat = i * THREADS + tid;
        const int k = flat >> 4;
        const int c = flat & 15;
        cp16(Bs_a[0] + k * 256 + ((c ^ (k & 7)) << 4), Wsrc + (size_t)k * NN + c * 8);
    }
    #pragma unroll
    for (int i = 0; i < 8; i++) {
        const int flat = i * THREADS + tid;
        const int m = flat >> 4;
        const int c = flat & 15;
        cp16(As_a + m * 256 + ((c ^ (m & 7)) << 4), Ysrc + (size_t)m * DD + c * 8);
    }
    CP_COMMIT();
    if (tid < TM) sInd[tid] = Ind[(size_t)(b * HH + h) * KDIM + k0 + tid];
    CP_WAIT0();
    __syncthreads();

    float* outb = out + (size_t)b * TT * NN;

    // per-warp scatter rows
    int t0s[4], t1s[4];
    #pragma unroll
    for (int im = 0; im < 4; im++) {
        const int mrow = wm * 64 + im * 16;
        t0s[im] = sInd[mrow + g];
        t1s[im] = sInd[mrow + g + 8];
    }

    const int a_ml_base = wm * 64 + ((lane >> 3) & 1) * 8 + (lane & 7);
    const int a_chi     = lane >> 4;
    const int b_kl_base = ((lane >> 3) & 1) * 8 + (lane & 7);

    #pragma unroll 1
    for (int nc = 0; nc < NCHUNK; nc++) {
        const int buf = nc & 1;
        const bool has_next = (nc + 1 < NCHUNK);

        // ---- Issue cp.async for next B chunk into other buffer ----
        if (has_next) {
            const __half* Wn = Wsrc + (size_t)(nc + 1) * TN;
            #pragma unroll
            for (int i = 0; i < 8; i++) {
                const int flat = i * THREADS + tid;
                const int k = flat >> 4;
                const int c = flat & 15;
                cp16(Bs_a[buf ^ 1] + k * 256 + ((c ^ (k & 7)) << 4),
                     Wn + (size_t)k * NN + c * 8);
            }
            CP_COMMIT();
        }

        // ---- Compute: warp tile 64m x 32n = 4(im) x 4(in) x 8(kt) ----
        float acc[4][4][4];
        #pragma unroll
        for (int im = 0; im < 4; im++)
            #pragma unroll
            for (int in = 0; in < 4; in++)
                #pragma unroll
                for (int c = 0; c < 4; c++) acc[im][in][c] = 0.f;

        #pragma unroll
        for (int kt = 0; kt < 8; kt++) {
            uint32_t a[4][4], bfr[2][4];
            #pragma unroll
            for (int im = 0; im < 4; im++) {
                const int ml = a_ml_base + im * 16;
                const int c  = kt * 2 + a_chi;
                ldsm_x4(a[im], As_a + ml * 256 + ((c ^ (ml & 7)) << 4));
            }
            #pragma unroll
            for (int inp = 0; inp < 2; inp++) {
                const int kl = kt * 16 + b_kl_base;
                const int c  = wn * 4 + inp * 2 + (lane >> 4);
                ldsm_x4_t(bfr[inp], Bs_a[buf] + kl * 256 + ((c ^ (kl & 7)) << 4));
            }
            #pragma unroll
            for (int in = 0; in < 4; in++) {
                const uint32_t bb[2] = { bfr[in >> 1][(in & 1) * 2],
                                         bfr[in >> 1][(in & 1) * 2 + 1] };
                #pragma unroll
                for (int im = 0; im < 4; im++)
                    mma_f16(acc[im][in], a[im], bb);
            }
        }

        // ---- Epilogue: vectorized scatter-add ----
        const int colb = nc * TN + wn * 32 + tig * 2;
        #pragma unroll
        for (int im = 0; im < 4; im++) {
            float* r0 = outb + (size_t)t0s[im] * NN + colb;
            float* r1 = outb + (size_t)t1s[im] * NN + colb;
            #pragma unroll
            for (int in = 0; in < 4; in++) {
                red_v2(r0 + in * 8, acc[im][in][0], acc[im][in][1]);
                red_v2(r1 + in * 8, acc[im][in][2], acc[im][in][3]);
            }
        }

        if (has_next) {
            CP_WAIT0();
            __syncthreads();
        }
    }
}

extern "C" void kernel_launch(void* const* d_in, const int* in_sizes, int n_in,
                              void* d_out, int out_size) {
    const float* Y   = (const float*)d_in[0];
    const int*   Ind = (const int*)d_in[1];
    const float* W   = (const float*)d_in[n_in - 1];
    float* out = (float*)d_out;

    void *wh_p = nullptr, *yh_p = nullptr;
    cudaGetSymbolAddress(&wh_p, g_Wh);
    cudaGetSymbolAddress(&yh_p, g_Yh);

    // fused: W->fp16, Y->fp16, zero output (single launch)
    const int nzero4 = (BB * TT * NN) / 4;
    const int zblocks = (nzero4 + 511) / 512;
    prologue_kernel<<<WCONV_BLOCKS + YCONV_BLOCKS + zblocks, 512>>>(
        W, (__half*)wh_p, Y, (__half*)yh_p, (float4*)out, nzero4);

    cudaFuncSetAttribute(expert_scatter_f16,
                         cudaFuncAttributeMaxDynamicSharedMemorySize, SMEM_BYTES);
    dim3 grid(KDIM / TM, HH, BB);   // 8 x 16 x 8 = 1024 CTAs
    expert_scatter_f16<<<grid, THREADS, SMEM_BYTES>>>(Ind, out);
}

// round 15
// speedup vs baseline: 1.0159x; 1.0159x over previous
#include <cuda_runtime.h>
#include <cuda_fp16.h>
#include <cstdint>

// ExpertScatter: out[b, Ind[b,h,k], :] += Y[b,h,k,:] @ W[h]
// R15 = exact R9 (session-best 201.2us): fp16 mma, TM=128 / 256-thread CTAs,
//       2 CTAs/SM (overlapping pipelines), W pre-converted to fp16 scratch +
//       cp.async B staging, LDG f32 A staging, red.v2 epilogue.

#define BB 8
#define HH 16
#define KDIM 1024
#define DD 128
#define NN 1024
#define TT 4096

#define TM 128
#define TN 128
#define NCHUNK 8
#define THREADS 256

#define AS_BYTES (TM * DD * 2)                 // 32768
#define BS_BYTES (DD * TN * 2)                 // 32768
#define SMEM_BYTES (AS_BYTES + 2 * BS_BYTES)   // 98304  (2 CTAs = 192KB <= 227KB)

__device__ __align__(16) __half g_Wh[HH * DD * NN];   // 4 MB fp16 W scratch

__global__ void zero_out_kernel(float4* __restrict__ p, int n4) {
    int i = blockIdx.x * blockDim.x + threadIdx.x;
    if (i < n4) p[i] = make_float4(0.f, 0.f, 0.f, 0.f);
}

__device__ __forceinline__ uint32_t pack_h2(float a, float b) {
    __half2 h = __floats2half2_rn(a, b);
    return *(uint32_t*)&h;
}

__global__ void convert_w_kernel(const float* __restrict__ src, __half* __restrict__ dst, int n8) {
    int i = blockIdx.x * blockDim.x + threadIdx.x;
    if (i >= n8) return;
    const float4 v0 = ((const float4*)src)[2 * i];
    const float4 v1 = ((const float4*)src)[2 * i + 1];
    uint4 w = { pack_h2(v0.x, v0.y), pack_h2(v0.z, v0.w),
                pack_h2(v1.x, v1.y), pack_h2(v1.z, v1.w) };
    ((uint4*)dst)[i] = w;
}

__device__ __forceinline__ uint32_t smem_u32(const void* p) {
    uint32_t a;
    asm("{ .reg .u64 t; cvta.to.shared.u64 t, %1; cvt.u32.u64 %0, t; }" : "=r"(a) : "l"(p));
    return a;
}
__device__ __forceinline__ void cp16(uint32_t dst, const void* src) {
    asm volatile("cp.async.cg.shared.global [%0], [%1], 16;" :: "r"(dst), "l"(src));
}
#define CP_COMMIT() asm volatile("cp.async.commit_group;" ::: "memory")
#define CP_WAIT0()  asm volatile("cp.async.wait_group 0;" ::: "memory")

__device__ __forceinline__ void ldsm_x4(uint32_t* r, uint32_t addr) {
    asm volatile("ldmatrix.sync.aligned.m8n8.x4.shared.b16 {%0,%1,%2,%3}, [%4];"
                 : "=r"(r[0]), "=r"(r[1]), "=r"(r[2]), "=r"(r[3]) : "r"(addr));
}
__device__ __forceinline__ void ldsm_x4_t(uint32_t* r, uint32_t addr) {
    asm volatile("ldmatrix.sync.aligned.m8n8.x4.trans.shared.b16 {%0,%1,%2,%3}, [%4];"
                 : "=r"(r[0]), "=r"(r[1]), "=r"(r[2]), "=r"(r[3]) : "r"(addr));
}
__device__ __forceinline__ void mma_f16(float* c, const uint32_t* a, const uint32_t* b) {
    asm volatile(
        "mma.sync.aligned.m16n8k16.row.col.f32.f16.f16.f32 "
        "{%0,%1,%2,%3}, {%4,%5,%6,%7}, {%8,%9}, {%0,%1,%2,%3};"
        : "+f"(c[0]), "+f"(c[1]), "+f"(c[2]), "+f"(c[3])
        : "r"(a[0]), "r"(a[1]), "r"(a[2]), "r"(a[3]), "r"(b[0]), "r"(b[1]));
}
__device__ __forceinline__ void red_v2(float* p, float x, float y) {
    asm volatile("red.global.add.v2.f32 [%0], {%1, %2};"
                 :: "l"(p), "f"(x), "f"(y) : "memory");
}

__global__ void __launch_bounds__(THREADS, 2)
expert_scatter_f16(const float* __restrict__ Y,
                   const int*   __restrict__ Ind,
                   float*       __restrict__ out) {
    const int b  = blockIdx.z;
    const int h  = blockIdx.y;
    const int k0 = blockIdx.x * TM;

    extern __shared__ char sm[];
    const uint32_t As_a = smem_u32(sm);
    const uint32_t Bs_a[2] = { As_a + AS_BYTES, As_a + AS_BYTES + BS_BYTES };
    __shared__ int sInd[TM];

    const int tid  = threadIdx.x;
    const int warp = tid >> 5;
    const int lane = tid & 31;
    const int g    = lane >> 2;
    const int tig  = lane & 3;
    const int wm   = warp >> 2;   // 0..1 : 64-row band
    const int wn   = warp & 3;    // 0..3 : 32-col band

    const __half* Wsrc = g_Wh + (size_t)h * DD * NN;

    // ---- Issue cp.async for B chunk 0 first (longest latency) ----
    #pragma unroll
    for (int i = 0; i < 8; i++) {
        const int flat = i * THREADS + tid;
        const int k = flat >> 4;
        const int c = flat & 15;
        cp16(Bs_a[0] + k * 256 + ((c ^ (k & 7)) << 4), Wsrc + (size_t)k * NN + c * 8);
    }
    CP_COMMIT();

    // ---- Stage A: Y[128m x 128k] f32 -> fp16 [m][k], 16B chunks, c ^= m&7 ----
    const float* Yp = Y + ((size_t)(b * HH + h) * KDIM + k0) * DD;
    #pragma unroll
    for (int i = 0; i < 8; i++) {
        const int flat = i * THREADS + tid;
        const int m = flat >> 4;
        const int c = flat & 15;
        const float4 v0 = *(const float4*)(Yp + (size_t)m * DD + c * 8);
        const float4 v1 = *(const float4*)(Yp + (size_t)m * DD + c * 8 + 4);
        uint4 w = { pack_h2(v0.x, v0.y), pack_h2(v0.z, v0.w),
                    pack_h2(v1.x, v1.y), pack_h2(v1.z, v1.w) };
        asm volatile("st.shared.v4.b32 [%0], {%1,%2,%3,%4};"
                     :: "r"(As_a + m * 256 + ((c ^ (m & 7)) << 4)),
                        "r"(w.x), "r"(w.y), "r"(w.z), "r"(w.w) : "memory");
    }
    if (tid < TM) sInd[tid] = Ind[(size_t)(b * HH + h) * KDIM + k0 + tid];

    CP_WAIT0();
    __syncthreads();

    float* outb = out + (size_t)b * TT * NN;

    // per-warp scatter rows
    int t0s[4], t1s[4];
    #pragma unroll
    for (int im = 0; im < 4; im++) {
        const int mrow = wm * 64 + im * 16;
        t0s[im] = sInd[mrow + g];
        t1s[im] = sInd[mrow + g + 8];
    }

    const int a_ml_base = wm * 64 + ((lane >> 3) & 1) * 8 + (lane & 7);
    const int a_chi     = lane >> 4;
    const int b_kl_base = ((lane >> 3) & 1) * 8 + (lane & 7);

    #pragma unroll 1
    for (int nc = 0; nc < NCHUNK; nc++) {
        const int buf = nc & 1;
        const bool has_next = (nc + 1 < NCHUNK);

        // ---- Issue cp.async for next B chunk into other buffer ----
        if (has_next) {
            const __half* Wn = Wsrc + (size_t)(nc + 1) * TN;
            #pragma unroll
            for (int i = 0; i < 8; i++) {
                const int flat = i * THREADS + tid;
                const int k = flat >> 4;
                const int c = flat & 15;
                cp16(Bs_a[buf ^ 1] + k * 256 + ((c ^ (k & 7)) << 4),
                     Wn + (size_t)k * NN + c * 8);
            }
            CP_COMMIT();
        }

        // ---- Compute: warp tile 64m x 32n = 4(im) x 4(in) x 8(kt) ----
        float acc[4][4][4];
        #pragma unroll
        for (int im = 0; im < 4; im++)
            #pragma unroll
            for (int in = 0; in < 4; in++)
                #pragma unroll
                for (int c = 0; c < 4; c++) acc[im][in][c] = 0.f;

        #pragma unroll
        for (int kt = 0; kt < 8; kt++) {
            uint32_t a[4][4], bfr[2][4];
            #pragma unroll
            for (int im = 0; im < 4; im++) {
                const int ml = a_ml_base + im * 16;
                const int c  = kt * 2 + a_chi;
                ldsm_x4(a[im], As_a + ml * 256 + ((c ^ (ml & 7)) << 4));
            }
            #pragma unroll
            for (int inp = 0; inp < 2; inp++) {
                const int kl = kt * 16 + b_kl_base;
                const int c  = wn * 4 + inp * 2 + (lane >> 4);
                ldsm_x4_t(bfr[inp], Bs_a[buf] + kl * 256 + ((c ^ (kl & 7)) << 4));
            }
            #pragma unroll
            for (int in = 0; in < 4; in++) {
                const uint32_t bb[2] = { bfr[in >> 1][(in & 1) * 2],
                                         bfr[in >> 1][(in & 1) * 2 + 1] };
                #pragma unroll
                for (int im = 0; im < 4; im++)
                    mma_f16(acc[im][in], a[im], bb);
            }
        }

        // ---- Epilogue: vectorized scatter-add ----
        const int colb = nc * TN + wn * 32 + tig * 2;
        #pragma unroll
        for (int im = 0; im < 4; im++) {
            float* r0 = outb + (size_t)t0s[im] * NN + colb;
            float* r1 = outb + (size_t)t1s[im] * NN + colb;
            #pragma unroll
            for (int in = 0; in < 4; in++) {
                red_v2(r0 + in * 8, acc[im][in][0], acc[im][in][1]);
                red_v2(r1 + in * 8, acc[im][in][2], acc[im][in][3]);
            }
        }

        if (has_next) {
            CP_WAIT0();
            __syncthreads();
        }
    }
}

extern "C" void kernel_launch(void* const* d_in, const int* in_sizes, int n_in,
                              void* d_out, int out_size) {
    const float* Y   = (const float*)d_in[0];
    const int*   Ind = (const int*)d_in[1];
    const float* W   = (const float*)d_in[n_in - 1];
    float* out = (float*)d_out;

    void* wh_p = nullptr;
    cudaGetSymbolAddress(&wh_p, g_Wh);

    const int n4 = (BB * TT * NN) / 4;
    zero_out_kernel<<<(n4 + 511) / 512, 512>>>((float4*)out, n4);

    const int nw8 = (HH * DD * NN) / 8;
    convert_w_kernel<<<(nw8 + 511) / 512, 512>>>(W, (__half*)wh_p, nw8);

    cudaFuncSetAttribute(expert_scatter_f16,
                         cudaFuncAttributeMaxDynamicSharedMemorySize, SMEM_BYTES);
    dim3 grid(KDIM / TM, HH, BB);   // 8 x 16 x 8 = 1024 CTAs
    expert_scatter_f16<<<grid, THREADS, SMEM_BYTES>>>(Y, Ind, out);
}

// round 16
// speedup vs baseline: 1.5692x; 1.5446x over previous
#include <cuda_runtime.h>
#include <cuda_fp16.h>
#include <cstdint>

// ExpertScatter: out[b, Ind[b,h,k], :] += Y[b,h,k,:] @ W[h]
// R16 = champion config (R9/R13 main kernel, measured 178-182us in healthy
//       windows) + R13 fused zero/convert prologue (lowest measured overhead).
//       fp16 mma, TM=128/TN=128, 256 thr, 2 CTAs/SM, cp.async B staging from
//       fp16 W scratch, LDG f32 A staging, red.v2 epilogue.

#define BB 8
#define HH 16
#define KDIM 1024
#define DD 128
#define NN 1024
#define TT 4096

#define TM 128
#define TN 128
#define NCHUNK 8
#define THREADS 256

#define AS_BYTES (TM * DD * 2)                 // 32768
#define BS_BYTES (DD * TN * 2)                 // 32768
#define SMEM_BYTES (AS_BYTES + 2 * BS_BYTES)   // 98304 (2 CTAs = 192KB <= 227KB)

__device__ __align__(16) __half g_Wh[HH * DD * NN];   // 4 MB fp16 W scratch

__device__ __forceinline__ uint32_t pack_h2(float a, float b) {
    __half2 h = __floats2half2_rn(a, b);
    return *(uint32_t*)&h;
}

// fused prologue: blocks [0,512) convert W f32->f16 ; rest zero the output
#define CONV_BLOCKS 512
__global__ void prologue_kernel(const float* __restrict__ W, __half* __restrict__ Wh,
                                float4* __restrict__ out, int nzero4) {
    if (blockIdx.x < CONV_BLOCKS) {
        const int i = blockIdx.x * 512 + threadIdx.x;   // 262144 uint4
        const float4 v0 = ((const float4*)W)[2 * i];
        const float4 v1 = ((const float4*)W)[2 * i + 1];
        uint4 w = { pack_h2(v0.x, v0.y), pack_h2(v0.z, v0.w),
                    pack_h2(v1.x, v1.y), pack_h2(v1.z, v1.w) };
        ((uint4*)Wh)[i] = w;
    } else {
        const int j = (blockIdx.x - CONV_BLOCKS) * 512 + threadIdx.x;
        if (j < nzero4) out[j] = make_float4(0.f, 0.f, 0.f, 0.f);
    }
}

__device__ __forceinline__ uint32_t smem_u32(const void* p) {
    uint32_t a;
    asm("{ .reg .u64 t; cvta.to.shared.u64 t, %1; cvt.u32.u64 %0, t; }" : "=r"(a) : "l"(p));
    return a;
}
__device__ __forceinline__ void cp16(uint32_t dst, const void* src) {
    asm volatile("cp.async.cg.shared.global [%0], [%1], 16;" :: "r"(dst), "l"(src));
}
#define CP_COMMIT() asm volatile("cp.async.commit_group;" ::: "memory")
#define CP_WAIT0()  asm volatile("cp.async.wait_group 0;" ::: "memory")

__device__ __forceinline__ void ldsm_x4(uint32_t* r, uint32_t addr) {
    asm volatile("ldmatrix.sync.aligned.m8n8.x4.shared.b16 {%0,%1,%2,%3}, [%4];"
                 : "=r"(r[0]), "=r"(r[1]), "=r"(r[2]), "=r"(r[3]) : "r"(addr));
}
__device__ __forceinline__ void ldsm_x4_t(uint32_t* r, uint32_t addr) {
    asm volatile("ldmatrix.sync.aligned.m8n8.x4.trans.shared.b16 {%0,%1,%2,%3}, [%4];"
                 : "=r"(r[0]), "=r"(r[1]), "=r"(r[2]), "=r"(r[3]) : "r"(addr));
}
__device__ __forceinline__ void mma_f16(float* c, const uint32_t* a, const uint32_t* b) {
    asm volatile(
        "mma.sync.aligned.m16n8k16.row.col.f32.f16.f16.f32 "
        "{%0,%1,%2,%3}, {%4,%5,%6,%7}, {%8,%9}, {%0,%1,%2,%3};"
        : "+f"(c[0]), "+f"(c[1]), "+f"(c[2]), "+f"(c[3])
        : "r"(a[0]), "r"(a[1]), "r"(a[2]), "r"(a[3]), "r"(b[0]), "r"(b[1]));
}
__device__ __forceinline__ void red_v2(float* p, float x, float y) {
    asm volatile("red.global.add.v2.f32 [%0], {%1, %2};"
                 :: "l"(p), "f"(x), "f"(y) : "memory");
}

__global__ void __launch_bounds__(THREADS, 2)
expert_scatter_f16(const float* __restrict__ Y,
                   const int*   __restrict__ Ind,
                   float*       __restrict__ out) {
    const int b  = blockIdx.z;
    const int h  = blockIdx.y;
    const int k0 = blockIdx.x * TM;

    extern __shared__ char sm[];
    const uint32_t As_a = smem_u32(sm);
    const uint32_t Bs_a[2] = { As_a + AS_BYTES, As_a + AS_BYTES + BS_BYTES };
    __shared__ int sInd[TM];

    const int tid  = threadIdx.x;
    const int warp = tid >> 5;
    const int lane = tid & 31;
    const int g    = lane >> 2;
    const int tig  = lane & 3;
    const int wm   = warp >> 2;   // 0..1 : 64-row band
    const int wn   = warp & 3;    // 0..3 : 32-col band

    const __half* Wsrc = g_Wh + (size_t)h * DD * NN;

    // ---- Issue cp.async for B chunk 0 first (longest latency) ----
    #pragma unroll
    for (int i = 0; i < 8; i++) {
        const int flat = i * THREADS + tid;
        const int k = flat >> 4;
        const int c = flat & 15;
        cp16(Bs_a[0] + k * 256 + ((c ^ (k & 7)) << 4), Wsrc + (size_t)k * NN + c * 8);
    }
    CP_COMMIT();

    // ---- Stage A: Y[128m x 128k] f32 -> fp16 [m][k], 16B chunks, c ^= m&7 ----
    const float* Yp = Y + ((size_t)(b * HH + h) * KDIM + k0) * DD;
    #pragma unroll
    for (int i = 0; i < 8; i++) {
        const int flat = i * THREADS + tid;
        const int m = flat >> 4;
        const int c = flat & 15;
        const float4 v0 = *(const float4*)(Yp + (size_t)m * DD + c * 8);
        const float4 v1 = *(const float4*)(Yp + (size_t)m * DD + c * 8 + 4);
        uint4 w = { pack_h2(v0.x, v0.y), pack_h2(v0.z, v0.w),
                    pack_h2(v1.x, v1.y), pack_h2(v1.z, v1.w) };
        asm volatile("st.shared.v4.b32 [%0], {%1,%2,%3,%4};"
                     :: "r"(As_a + m * 256 + ((c ^ (m & 7)) << 4)),
                        "r"(w.x), "r"(w.y), "r"(w.z), "r"(w.w) : "memory");
    }
    if (tid < TM) sInd[tid] = Ind[(size_t)(b * HH + h) * KDIM + k0 + tid];

    CP_WAIT0();
    __syncthreads();

    float* outb = out + (size_t)b * TT * NN;

    // per-warp scatter rows
    int t0s[4], t1s[4];
    #pragma unroll
    for (int im = 0; im < 4; im++) {
        const int mrow = wm * 64 + im * 16;
        t0s[im] = sInd[mrow + g];
        t1s[im] = sInd[mrow + g + 8];
    }

    const int a_ml_base = wm * 64 + ((lane >> 3) & 1) * 8 + (lane & 7);
    const int a_chi     = lane >> 4;
    const int b_kl_base = ((lane >> 3) & 1) * 8 + (lane & 7);

    #pragma unroll 1
    for (int nc = 0; nc < NCHUNK; nc++) {
        const int buf = nc & 1;
        const bool has_next = (nc + 1 < NCHUNK);

        // ---- Issue cp.async for next B chunk into other buffer ----
        if (has_next) {
            const __half* Wn = Wsrc + (size_t)(nc + 1) * TN;
            #pragma unroll
            for (int i = 0; i < 8; i++) {
                const int flat = i * THREADS + tid;
                const int k = flat >> 4;
                const int c = flat & 15;
                cp16(Bs_a[buf ^ 1] + k * 256 + ((c ^ (k & 7)) << 4),
                     Wn + (size_t)k * NN + c * 8);
            }
            CP_COMMIT();
        }

        // ---- Compute: warp tile 64m x 32n = 4(im) x 4(in) x 8(kt) ----
        float acc[4][4][4];
        #pragma unroll
        for (int im = 0; im < 4; im++)
            #pragma unroll
            for (int in = 0; in < 4; in++)
                #pragma unroll
                for (int c = 0; c < 4; c++) acc[im][in][c] = 0.f;

        #pragma unroll
        for (int kt = 0; kt < 8; kt++) {
            uint32_t a[4][4], bfr[2][4];
            #pragma unroll
            for (int im = 0; im < 4; im++) {
                const int ml = a_ml_base + im * 16;
                const int c  = kt * 2 + a_chi;
                ldsm_x4(a[im], As_a + ml * 256 + ((c ^ (ml & 7)) << 4));
            }
            #pragma unroll
            for (int inp = 0; inp < 2; inp++) {
                const int kl = kt * 16 + b_kl_base;
                const int c  = wn * 4 + inp * 2 + (lane >> 4);
                ldsm_x4_t(bfr[inp], Bs_a[buf] + kl * 256 + ((c ^ (kl & 7)) << 4));
            }
            #pragma unroll
            for (int in = 0; in < 4; in++) {
                const uint32_t bb[2] = { bfr[in >> 1][(in & 1) * 2],
                                         bfr[in >> 1][(in & 1) * 2 + 1] };
                #pragma unroll
                for (int im = 0; im < 4; im++)
                    mma_f16(acc[im][in], a[im], bb);
            }
        }

        // ---- Epilogue: vectorized scatter-add ----
        const int colb = nc * TN + wn * 32 + tig * 2;
        #pragma unroll
        for (int im = 0; im < 4; im++) {
            float* r0 = outb + (size_t)t0s[im] * NN + colb;
            float* r1 = outb + (size_t)t1s[im] * NN + colb;
            #pragma unroll
            for (int in = 0; in < 4; in++) {
                red_v2(r0 + in * 8, acc[im][in][0], acc[im][in][1]);
                red_v2(r1 + in * 8, acc[im][in][2], acc[im][in][3]);
            }
        }

        if (has_next) {
            CP_WAIT0();
            __syncthreads();
        }
    }
}

extern "C" void kernel_launch(void* const* d_in, const int* in_sizes, int n_in,
                              void* d_out, int out_size) {
    const float* Y   = (const float*)d_in[0];
    const int*   Ind = (const int*)d_in[1];
    const float* W   = (const float*)d_in[n_in - 1];
    float* out = (float*)d_out;

    void* wh_p = nullptr;
    cudaGetSymbolAddress(&wh_p, g_Wh);

    // fused zero + W convert (single launch)
    const int nzero4 = (BB * TT * NN) / 4;
    const int zblocks = (nzero4 + 511) / 512;
    prologue_kernel<<<CONV_BLOCKS + zblocks, 512>>>(W, (__half*)wh_p,
                                                    (float4*)out, nzero4);

    cudaFuncSetAttribute(expert_scatter_f16,
                         cudaFuncAttributeMaxDynamicSharedMemorySize, SMEM_BYTES);
    dim3 grid(KDIM / TM, HH, BB);   // 8 x 16 x 8 = 1024 CTAs
    expert_scatter_f16<<<grid, THREADS, SMEM_BYTES>>>(Y, Ind, out);
}

// round 17
// speedup vs baseline: 1.5884x; 1.0122x over previous
#include <cuda_runtime.h>
#include <cuda_fp16.h>
#include <cstdint>

// ExpertScatter: out[b, Ind[b,h,k], :] += Y[b,h,k,:] @ W[h]
// R17: champion platform + per-warp-pair private B slices with 64-thread
//      named barriers (no CTA-wide sync in main loop). fp16 mma, TM=128,
//      2 CTAs/SM, cp.async B staging from fp16 W scratch, red.v2 epilogue.

#define BB 8
#define HH 16
#define KDIM 1024
#define DD 128
#define NN 1024
#define TT 4096

#define TM 128
#define TN 128           // chunk width (per pair slice = 32)
#define NCHUNK 8
#define THREADS 256

#define AS_BYTES (TM * DD * 2)       // 32768
#define BSP_BYTES (DD * 32 * 2)      // 8192 per pair per buffer
#define SMEM_BYTES (AS_BYTES + 4 * 2 * BSP_BYTES)   // 98304 (2 CTAs = 192KB)

__device__ __align__(16) __half g_Wh[HH * DD * NN];   // 4 MB fp16 W scratch

__device__ __forceinline__ uint32_t pack_h2(float a, float b) {
    __half2 h = __floats2half2_rn(a, b);
    return *(uint32_t*)&h;
}

// fused prologue: blocks [0,512) convert W f32->f16 ; rest zero the output
#define CONV_BLOCKS 512
__global__ void prologue_kernel(const float* __restrict__ W, __half* __restrict__ Wh,
                                float4* __restrict__ out, int nzero4) {
    if (blockIdx.x < CONV_BLOCKS) {
        const int i = blockIdx.x * 512 + threadIdx.x;
        const float4 v0 = ((const float4*)W)[2 * i];
        const float4 v1 = ((const float4*)W)[2 * i + 1];
        uint4 w = { pack_h2(v0.x, v0.y), pack_h2(v0.z, v0.w),
                    pack_h2(v1.x, v1.y), pack_h2(v1.z, v1.w) };
        ((uint4*)Wh)[i] = w;
    } else {
        const int j = (blockIdx.x - CONV_BLOCKS) * 512 + threadIdx.x;
        if (j < nzero4) out[j] = make_float4(0.f, 0.f, 0.f, 0.f);
    }
}

__device__ __forceinline__ uint32_t smem_u32(const void* p) {
    uint32_t a;
    asm("{ .reg .u64 t; cvta.to.shared.u64 t, %1; cvt.u32.u64 %0, t; }" : "=r"(a) : "l"(p));
    return a;
}
__device__ __forceinline__ void cp16(uint32_t dst, const void* src) {
    asm volatile("cp.async.cg.shared.global [%0], [%1], 16;" :: "r"(dst), "l"(src));
}
#define CP_COMMIT() asm volatile("cp.async.commit_group;" ::: "memory")
#define CP_WAIT0()  asm volatile("cp.async.wait_group 0;" ::: "memory")
#define BAR_PAIR(id) asm volatile("bar.sync %0, 64;" :: "r"(id) : "memory")

__device__ __forceinline__ void ldsm_x4(uint32_t* r, uint32_t addr) {
    asm volatile("ldmatrix.sync.aligned.m8n8.x4.shared.b16 {%0,%1,%2,%3}, [%4];"
                 : "=r"(r[0]), "=r"(r[1]), "=r"(r[2]), "=r"(r[3]) : "r"(addr));
}
__device__ __forceinline__ void ldsm_x4_t(uint32_t* r, uint32_t addr) {
    asm volatile("ldmatrix.sync.aligned.m8n8.x4.trans.shared.b16 {%0,%1,%2,%3}, [%4];"
                 : "=r"(r[0]), "=r"(r[1]), "=r"(r[2]), "=r"(r[3]) : "r"(addr));
}
__device__ __forceinline__ void mma_f16(float* c, const uint32_t* a, const uint32_t* b) {
    asm volatile(
        "mma.sync.aligned.m16n8k16.row.col.f32.f16.f16.f32 "
        "{%0,%1,%2,%3}, {%4,%5,%6,%7}, {%8,%9}, {%0,%1,%2,%3};"
        : "+f"(c[0]), "+f"(c[1]), "+f"(c[2]), "+f"(c[3])
        : "r"(a[0]), "r"(a[1]), "r"(a[2]), "r"(a[3]), "r"(b[0]), "r"(b[1]));
}
__device__ __forceinline__ void red_v2(float* p, float x, float y) {
    asm volatile("red.global.add.v2.f32 [%0], {%1, %2};"
                 :: "l"(p), "f"(x), "f"(y) : "memory");
}

__global__ void __launch_bounds__(THREADS, 2)
expert_scatter_f16(const float* __restrict__ Y,
                   const int*   __restrict__ Ind,
                   float*       __restrict__ out) {
    const int b  = blockIdx.z;
    const int h  = blockIdx.y;
    const int k0 = blockIdx.x * TM;

    extern __shared__ char sm[];
    const uint32_t As_a = smem_u32(sm);
    __shared__ int sInd[TM];

    const int tid  = threadIdx.x;
    const int warp = tid >> 5;
    const int lane = tid & 31;
    const int g    = lane >> 2;
    const int tig  = lane & 3;
    const int wm   = warp >> 2;   // 0..1 : 64-row band
    const int wn   = warp & 3;    // 0..3 : 32-col band (pair id)
    const int ptid = wm * 32 + lane;   // 0..63 within the wn-pair

    // per-pair B buffers
    const uint32_t Bp_a[2] = { As_a + AS_BYTES + (uint32_t)(wn * 2 + 0) * BSP_BYTES,
                               As_a + AS_BYTES + (uint32_t)(wn * 2 + 1) * BSP_BYTES };

    const __half* Wsrc = g_Wh + (size_t)h * DD * NN;

    // ---- Stage pair B slice of chunk 0: [128k x 32n], row 64B, swizzled ----
    #pragma unroll
    for (int i = 0; i < 8; i++) {
        const int flat = i * 64 + ptid;       // 512 pieces of 16B
        const int k = flat >> 2;
        const int c = flat & 3;
        cp16(Bp_a[0] + k * 64 + ((c ^ ((k >> 1) & 3)) << 4),
             Wsrc + (size_t)k * NN + wn * 32 + c * 8);
    }
    CP_COMMIT();

    // ---- Stage A: Y[128m x 128k] f32 -> fp16 [m][k], 16B chunks, c ^= m&7 ----
    const float* Yp = Y + ((size_t)(b * HH + h) * KDIM + k0) * DD;
    #pragma unroll
    for (int i = 0; i < 8; i++) {
        const int flat = i * THREADS + tid;
        const int m = flat >> 4;
        const int c = flat & 15;
        const float4 v0 = *(const float4*)(Yp + (size_t)m * DD + c * 8);
        const float4 v1 = *(const float4*)(Yp + (size_t)m * DD + c * 8 + 4);
        uint4 w = { pack_h2(v0.x, v0.y), pack_h2(v0.z, v0.w),
                    pack_h2(v1.x, v1.y), pack_h2(v1.z, v1.w) };
        asm volatile("st.shared.v4.b32 [%0], {%1,%2,%3,%4};"
                     :: "r"(As_a + m * 256 + ((c ^ (m & 7)) << 4)),
                        "r"(w.x), "r"(w.y), "r"(w.z), "r"(w.w) : "memory");
    }
    if (tid < TM) sInd[tid] = Ind[(size_t)(b * HH + h) * KDIM + k0 + tid];

    CP_WAIT0();
    __syncthreads();   // A + sInd + all pairs' B0 visible; last CTA-wide sync

    float* outb = out + (size_t)b * TT * NN;

    int t0s[4], t1s[4];
    #pragma unroll
    for (int im = 0; im < 4; im++) {
        const int mrow = wm * 64 + im * 16;
        t0s[im] = sInd[mrow + g];
        t1s[im] = sInd[mrow + g + 8];
    }

    const int a_ml_base = wm * 64 + ((lane >> 3) & 1) * 8 + (lane & 7);
    const int a_chi     = lane >> 4;
    const int b_kl_base = ((lane >> 3) & 1) * 8 + (lane & 7);
    const int bar_id    = wn + 1;

    #pragma unroll 1
    for (int nc = 0; nc < NCHUNK; nc++) {
        const int buf = nc & 1;
        const bool has_next = (nc + 1 < NCHUNK);

        // ---- Stage pair B slice of next chunk into other buffer ----
        if (has_next) {
            const __half* Wn = Wsrc + (size_t)(nc + 1) * TN;
            #pragma unroll
            for (int i = 0; i < 8; i++) {
                const int flat = i * 64 + ptid;
                const int k = flat >> 2;
                const int c = flat & 3;
                cp16(Bp_a[buf ^ 1] + k * 64 + ((c ^ ((k >> 1) & 3)) << 4),
                     Wn + (size_t)k * NN + wn * 32 + c * 8);
            }
            CP_COMMIT();
        }

        // ---- Compute: warp tile 64m x 32n = 4(im) x 4(in) x 8(kt) ----
        float acc[4][4][4];
        #pragma unroll
        for (int im = 0; im < 4; im++)
            #pragma unroll
            for (int in = 0; in < 4; in++)
                #pragma unroll
                for (int c = 0; c < 4; c++) acc[im][in][c] = 0.f;

        #pragma unroll
        for (int kt = 0; kt < 8; kt++) {
            uint32_t a[4][4], bfr[2][4];
            #pragma unroll
            for (int im = 0; im < 4; im++) {
                const int ml = a_ml_base + im * 16;
                const int c  = kt * 2 + a_chi;
                ldsm_x4(a[im], As_a + ml * 256 + ((c ^ (ml & 7)) << 4));
            }
            #pragma unroll
            for (int inp = 0; inp < 2; inp++) {
                const int kl = kt * 16 + b_kl_base;
                const int c  = inp * 2 + (lane >> 4);
                ldsm_x4_t(bfr[inp], Bp_a[buf] + kl * 64 + ((c ^ ((kl >> 1) & 3)) << 4));
            }
            #pragma unroll
            for (int in = 0; in < 4; in++) {
                const uint32_t bb[2] = { bfr[in >> 1][(in & 1) * 2],
                                         bfr[in >> 1][(in & 1) * 2 + 1] };
                #pragma unroll
                for (int im = 0; im < 4; im++)
                    mma_f16(acc[im][in], a[im], bb);
            }
        }

        // ---- Epilogue: vectorized scatter-add ----
        const int colb = nc * TN + wn * 32 + tig * 2;
        #pragma unroll
        for (int im = 0; im < 4; im++) {
            float* r0 = outb + (size_t)t0s[im] * NN + colb;
            float* r1 = outb + (size_t)t1s[im] * NN + colb;
            #pragma unroll
            for (int in = 0; in < 4; in++) {
                red_v2(r0 + in * 8, acc[im][in][0], acc[im][in][1]);
                red_v2(r1 + in * 8, acc[im][in][2], acc[im][in][3]);
            }
        }

        if (has_next) {
            CP_WAIT0();
            BAR_PAIR(bar_id);   // 64-thread pair barrier only
        }
    }
}

extern "C" void kernel_launch(void* const* d_in, const int* in_sizes, int n_in,
                              void* d_out, int out_size) {
    const float* Y   = (const float*)d_in[0];
    const int*   Ind = (const int*)d_in[1];
    const float* W   = (const float*)d_in[n_in - 1];
    float* out = (float*)d_out;

    void* wh_p = nullptr;
    cudaGetSymbolAddress(&wh_p, g_Wh);

    const int nzero4 = (BB * TT * NN) / 4;
    const int zblocks = (nzero4 + 511) / 512;
    prologue_kernel<<<CONV_BLOCKS + zblocks, 512>>>(W, (__half*)wh_p,
                                                    (float4*)out, nzero4);

    cudaFuncSetAttribute(expert_scatter_f16,
                         cudaFuncAttributeMaxDynamicSharedMemorySize, SMEM_BYTES);
    dim3 grid(KDIM / TM, HH, BB);   // 8 x 16 x 8 = 1024 CTAs
    expert_scatter_f16<<<grid, THREADS, SMEM_BYTES>>>(Y, Ind, out);
}